// round 11
// baseline (speedup 1.0000x reference)
#include <cuda_runtime.h>
#include <cuda_bf16.h>
#include <cstdint>

#define NB   8
#define NC   19
#define HW   512
#define NPIX (HW*HW)
#define NIMG 16
#define BIG  1e30f

#define OUTW 120
#define NSX  5
#define ROWS 16
#define NSY  (HW/ROWS)      // 32
#define WPI  (NSX*NSY)      // 160 warp-tiles per image pair
#define NBLK (NB*WPI/4)     // 320 blocks of 4 warps (each warp: 2 images)
#define BPI  (WPI/4)        // 40 blocks per pair

__device__ float g_prob[NIMG * NPIX];
__device__ float g_imA [NIMG * NPIX];
__device__ float g_imB [NIMG * NPIX];
__device__ float g_q   [NIMG * NPIX];
__device__ float g_partials[NBLK * 4];

// ---------------- kernel 1: softmax class-prob + teacher clip (float4) ----------
__global__ void prob_kernel(const float* __restrict__ logits,
                            const float* __restrict__ mask,
                            const int* __restrict__ cidx) {
    int t = blockIdx.x * blockDim.x + threadIdx.x;
    if (t >= NB * NPIX / 4) return;
    int b = t >> 16;
    int p = (t & 65535) << 2;
    const float* lp = logits + (size_t)b * NC * NPIX + p;

    float4 v[NC];
    #pragma unroll
    for (int c = 0; c < NC; c++) v[c] = *(const float4*)(lp + (size_t)c * NPIX);

    float4 m = v[0];
    #pragma unroll
    for (int c = 1; c < NC; c++) {
        m.x = fmaxf(m.x, v[c].x); m.y = fmaxf(m.y, v[c].y);
        m.z = fmaxf(m.z, v[c].z); m.w = fmaxf(m.w, v[c].w);
    }
    int ci = *cidx;
    float4 s = {0,0,0,0}, tg = {0,0,0,0};
    #pragma unroll
    for (int c = 0; c < NC; c++) {
        float4 e;
        e.x = __expf(v[c].x - m.x); e.y = __expf(v[c].y - m.y);
        e.z = __expf(v[c].z - m.z); e.w = __expf(v[c].w - m.w);
        s.x += e.x; s.y += e.y; s.z += e.z; s.w += e.w;
        if (c == ci) tg = e;
    }
    float4 pr;
    pr.x = fminf(fmaxf(tg.x / s.x, 0.f), 1.f);
    pr.y = fminf(fmaxf(tg.y / s.y, 0.f), 1.f);
    pr.z = fminf(fmaxf(tg.z / s.z, 0.f), 1.f);
    pr.w = fminf(fmaxf(tg.w / s.w, 0.f), 1.f);
    *(float4*)(g_prob + b * NPIX + p) = pr;

    float4 mk = *(const float4*)(mask + b * NPIX + p);
    mk.x = fminf(fmaxf(mk.x, 0.f), 1.f);
    mk.y = fminf(fmaxf(mk.y, 0.f), 1.f);
    mk.z = fminf(fmaxf(mk.z, 0.f), 1.f);
    mk.w = fminf(fmaxf(mk.w, 0.f), 1.f);
    *(float4*)(g_prob + (NB + b) * NPIX + p) = mk;
}

// ---------------- dual-image (f42) morphology primitives ---------------------------
struct f42 { float4 a, b; };

__device__ __forceinline__ float4 mmin3(float4 a, float4 b, float4 c) {
    float4 v;
    v.x = fminf(fminf(a.x, b.x), c.x);
    v.y = fminf(fminf(a.y, b.y), c.y);
    v.z = fminf(fminf(a.z, b.z), c.z);
    v.w = fminf(fminf(a.w, b.w), c.w);
    return v;
}
__device__ __forceinline__ float4 mmax3(float4 a, float4 b, float4 c) {
    float4 v;
    v.x = fmaxf(fmaxf(a.x, b.x), c.x);
    v.y = fmaxf(fmaxf(a.y, b.y), c.y);
    v.z = fmaxf(fmaxf(a.z, b.z), c.z);
    v.w = fmaxf(fmaxf(a.w, b.w), c.w);
    return v;
}

// horizontal 3-tap min on one float4 stream (2 shfl)
__device__ __forceinline__ float4 hmin(float4 v) {
    float vl = __shfl_up_sync(0xFFFFFFFFu, v.w, 1);
    float vr = __shfl_down_sync(0xFFFFFFFFu, v.x, 1);
    float m01 = fminf(v.x, v.y), m12 = fminf(v.y, v.z), m23 = fminf(v.z, v.w);
    float4 e;
    e.x = fminf(vl, m01);
    e.y = fminf(m01, v.z);
    e.z = fminf(m12, v.w);
    e.w = fminf(m23, vr);
    return e;
}
__device__ __forceinline__ float4 hmax(float4 v) {
    float vl = __shfl_up_sync(0xFFFFFFFFu, v.w, 1);
    float vr = __shfl_down_sync(0xFFFFFFFFu, v.x, 1);
    float m01 = fmaxf(v.x, v.y), m12 = fmaxf(v.y, v.z), m23 = fmaxf(v.z, v.w);
    float4 e;
    e.x = fmaxf(vl, m01);
    e.y = fmaxf(m01, v.z);
    e.z = fmaxf(m12, v.w);
    e.w = fmaxf(m23, vr);
    return e;
}

__device__ __forceinline__ f42 ero3(f42 p, f42 q, f42 r) {
    f42 e;
    e.a = hmin(mmin3(p.a, q.a, r.a));
    e.b = hmin(mmin3(p.b, q.b, r.b));
    return e;
}
__device__ __forceinline__ f42 dil3(f42 p, f42 q, f42 r) {
    f42 e;
    e.a = hmax(mmax3(p.a, q.a, r.a));
    e.b = hmax(mmax3(p.b, q.b, r.b));
    return e;
}

__device__ __forceinline__ float4 msel1(float4 v, bool in, float pad) {
    float4 r;
    r.x = in ? v.x : pad;
    r.y = in ? v.y : pad;
    r.z = in ? v.z : pad;
    r.w = in ? v.w : pad;
    return r;
}

template<bool EDGE>
__device__ __forceinline__ f42 mk(f42 v, bool in, float pad) {
    if (!EDGE) return v;
    f42 r;
    r.a = msel1(v.a, in, pad);
    r.b = msel1(v.b, in, pad);
    return r;
}

template<bool EDGE>
__device__ __forceinline__ f42 ld2(const float* __restrict__ bA,
                                   const float* __restrict__ bB,
                                   int q, int gx, bool ok) {
    f42 r;
    if (!EDGE) {
        r.a = *(const float4*)(bA + q * HW + gx);
        r.b = *(const float4*)(bB + q * HW + gx);
    } else if (ok && (unsigned)q < HW) {
        r.a = *(const float4*)(bA + q * HW + gx);
        r.b = *(const float4*)(bB + q * HW + gx);
    } else {
        r.a.x = r.a.y = r.a.z = r.a.w = BIG;
        r.b = r.a;
    }
    return r;
}

// ---------------- fused double-stage body, dual-image ------------------------------
template<bool EDGE>
__device__ __forceinline__ void fused_body(
    const float* __restrict__ baseA, const float* __restrict__ baseB,
    float* __restrict__ outA, float* __restrict__ outB,
    float* __restrict__ qA, float* __restrict__ qB,
    int r0, int gx, bool colIn, bool stl, bool init)
{
    #define VROW(rr) (colIn && ((unsigned)(rr) < HW))

    f42 imm3 = ld2<EDGE>(baseA, baseB, r0 - 3, gx, colIn);
    f42 imr[6];
    imr[4] = ld2<EDGE>(baseA, baseB, r0 - 2, gx, colIn);
    imr[5] = ld2<EDGE>(baseA, baseB, r0 - 1, gx, colIn);
    imr[0] = ld2<EDGE>(baseA, baseB, r0 + 0, gx, colIn);
    imr[1] = ld2<EDGE>(baseA, baseB, r0 + 1, gx, colIn);
    imr[2] = ld2<EDGE>(baseA, baseB, r0 + 2, gx, colIn);
    imr[3] = ld2<EDGE>(baseA, baseB, r0 + 3, gx, colIn);

    f42 e1[4], e2[3];
    f42 e1m2 = ero3(imm3, imr[4], imr[5]);
    e1[3] = ero3(imr[4], imr[5], imr[0]);
    e1[0] = ero3(imr[5], imr[0], imr[1]);
    e1[1] = ero3(imr[0], imr[1], imr[2]);

    {
        bool inA = VROW(r0 - 2);
        bool inB = VROW(r0 - 1);
        e2[2] = ero3(mk<EDGE>(e1m2, inA, BIG), mk<EDGE>(e1[3], inB, BIG),
                     mk<EDGE>(e1[0], colIn, BIG));
        e2[0] = ero3(mk<EDGE>(e1[3], inB, BIG), mk<EDGE>(e1[0], colIn, BIG),
                     mk<EDGE>(e1[1], colIn, BIG));
    }

    #pragma unroll
    for (int i = 0; i < ROWS; i++) {
        int r = r0 + i;
        imr[(i + 4) % 6] = ld2<EDGE>(baseA, baseB, r + 4, gx, colIn);

        int o = r * HW + gx;
        float4 qa, qb;
        if (stl && !init) {
            qa = *(const float4*)(qA + o);
            qb = *(const float4*)(qB + o);
        }

        bool inRm1 = VROW(r - 1);
        bool inRp1 = VROW(r + 1);
        bool inRp2 = VROW(r + 2);

        e1[(i + 2) % 4] = ero3(imr[(i + 1) % 6], imr[(i + 2) % 6], imr[(i + 3) % 6]);

        e2[(i + 1) % 3] = ero3(mk<EDGE>(e1[i % 4],       colIn, BIG),
                               mk<EDGE>(e1[(i + 1) % 4], inRp1, BIG),
                               mk<EDGE>(e1[(i + 2) % 4], inRp2, BIG));

        f42 d1 = dil3(mk<EDGE>(e1[(i + 3) % 4], inRm1, -BIG),
                      mk<EDGE>(e1[i % 4],       colIn, -BIG),
                      mk<EDGE>(e1[(i + 1) % 4], inRp1, -BIG));

        f42 d2 = dil3(mk<EDGE>(e2[(i + 2) % 3], inRm1, -BIG),
                      mk<EDGE>(e2[i % 3],       colIn, -BIG),
                      mk<EDGE>(e2[(i + 1) % 3], inRp1, -BIG));

        f42 ia = imr[i % 6];
        f42 eb = e1[i % 4];

        float4 daa, dab, dba, dbb;
        daa.x = fmaxf(ia.a.x - d1.a.x, 0.f); daa.y = fmaxf(ia.a.y - d1.a.y, 0.f);
        daa.z = fmaxf(ia.a.z - d1.a.z, 0.f); daa.w = fmaxf(ia.a.w - d1.a.w, 0.f);
        dab.x = fmaxf(ia.b.x - d1.b.x, 0.f); dab.y = fmaxf(ia.b.y - d1.b.y, 0.f);
        dab.z = fmaxf(ia.b.z - d1.b.z, 0.f); dab.w = fmaxf(ia.b.w - d1.b.w, 0.f);
        dba.x = fmaxf(eb.a.x - d2.a.x, 0.f); dba.y = fmaxf(eb.a.y - d2.a.y, 0.f);
        dba.z = fmaxf(eb.a.z - d2.a.z, 0.f); dba.w = fmaxf(eb.a.w - d2.a.w, 0.f);
        dbb.x = fmaxf(eb.b.x - d2.b.x, 0.f); dbb.y = fmaxf(eb.b.y - d2.b.y, 0.f);
        dbb.z = fmaxf(eb.b.z - d2.b.z, 0.f); dbb.w = fmaxf(eb.b.w - d2.b.w, 0.f);

        if (stl) {
            if (init) {
                qa.x = 1.f - daa.x; qa.y = 1.f - daa.y;
                qa.z = 1.f - daa.z; qa.w = 1.f - daa.w;
                qb.x = 1.f - dab.x; qb.y = 1.f - dab.y;
                qb.z = 1.f - dab.z; qb.w = 1.f - dab.w;
            } else {
                qa.x -= qa.x * daa.x; qa.y -= qa.y * daa.y;
                qa.z -= qa.z * daa.z; qa.w -= qa.w * daa.w;
                qb.x -= qb.x * dab.x; qb.y -= qb.y * dab.y;
                qb.z -= qb.z * dab.z; qb.w -= qb.w * dab.w;
            }
            qa.x -= qa.x * dba.x; qa.y -= qa.y * dba.y;
            qa.z -= qa.z * dba.z; qa.w -= qa.w * dba.w;
            qb.x -= qb.x * dbb.x; qb.y -= qb.y * dbb.y;
            qb.z -= qb.z * dbb.z; qb.w -= qb.w * dbb.w;
            *(float4*)(qA + o)   = qa;
            *(float4*)(qB + o)   = qb;
            *(float4*)(outA + o) = e2[i % 3].a;
            *(float4*)(outB + o) = e2[i % 3].b;
        }
    }
    #undef VROW
}

__global__ void __launch_bounds__(128, 3) fused_kernel(int srcsel, int dstsel, int init) {
    int w    = (blockIdx.x << 2) + (threadIdx.x >> 5);
    int lane = threadIdx.x & 31;
    int pair = w / WPI;                  // 0..7 (same for all warps of a block)
    int rem  = w - pair * WPI;
    int sx   = rem / NSY;
    int sy   = rem - sx * NSY;
    int x0   = sx * OUTW;
    int r0   = sy * ROWS;
    int gx   = x0 - 4 + (lane << 2);

    bool colIn = (gx >= 0) && (gx < HW);
    bool stl   = (gx >= x0) && (gx < x0 + OUTW) && (gx < HW);

    const float* src = (srcsel == 0) ? g_prob : (srcsel == 1 ? g_imA : g_imB);
    float*       dst = (dstsel == 1) ? g_imA : g_imB;

    const float* baseA = src + pair * NPIX;
    const float* baseB = src + (pair + 8) * NPIX;
    float* outA = dst + pair * NPIX;
    float* outB = dst + (pair + 8) * NPIX;
    float* qA   = g_q + pair * NPIX;
    float* qB   = g_q + (pair + 8) * NPIX;

    bool edge = (sx == 0) || (sx == NSX - 1) || (sy == 0) || (sy == NSY - 1);
    if (!edge) fused_body<false>(baseA, baseB, outA, outB, qA, qB, r0, gx, true,  stl, init != 0);
    else       fused_body<true >(baseA, baseB, outA, outB, qA, qB, r0, gx, colIn, stl, init != 0);
}

// ---------------- final stage FUSED with reduction, dual-image ---------------------
template<bool EDGE>
__device__ __forceinline__ void redstage_body(
    const float* __restrict__ baseA, const float* __restrict__ baseB,
    const float* __restrict__ qA, const float* __restrict__ qB,
    const float* __restrict__ ppA, const float* __restrict__ ppB,
    int r0, int gx, bool colIn, bool stl,
    float& s0a, float& s1a, float& s0b, float& s1b)
{
    f42 ring[6];
    #pragma unroll
    for (int j = 0; j < 6; j++) ring[j] = ld2<EDGE>(baseA, baseB, r0 - 2 + j, gx, colIn);

    bool inM1 = colIn && ((unsigned)(r0 - 1) < HW);
    f42 Eprev = mk<EDGE>(ero3(ring[0], ring[1], ring[2]), inM1, -BIG);
    f42 Ecur  = mk<EDGE>(ero3(ring[1], ring[2], ring[3]), colIn, -BIG);

    #pragma unroll
    for (int i = 0; i < ROWS; i++) {
        int r = r0 + i;
        ring[i % 6] = ld2<EDGE>(baseA, baseB, r + 4, gx, colIn);
        int o = r * HW + gx;
        float4 qa, qb, pa, pb;
        if (stl) {
            qa = *(const float4*)(qA + o);
            qb = *(const float4*)(qB + o);
            pa = *(const float4*)(ppA + o);
            pb = *(const float4*)(ppB + o);
        }

        bool inP1 = colIn && ((unsigned)(r + 1) < HW);
        f42 En = mk<EDGE>(ero3(ring[(i + 2) % 6], ring[(i + 3) % 6], ring[(i + 4) % 6]),
                          inP1, -BIG);
        f42 dd = dil3(Eprev, Ecur, En);
        f42 ic = ring[(i + 2) % 6];

        float4 da, db;
        da.x = fmaxf(ic.a.x - dd.a.x, 0.f); da.y = fmaxf(ic.a.y - dd.a.y, 0.f);
        da.z = fmaxf(ic.a.z - dd.a.z, 0.f); da.w = fmaxf(ic.a.w - dd.a.w, 0.f);
        db.x = fmaxf(ic.b.x - dd.b.x, 0.f); db.y = fmaxf(ic.b.y - dd.b.y, 0.f);
        db.z = fmaxf(ic.b.z - dd.b.z, 0.f); db.w = fmaxf(ic.b.w - dd.b.w, 0.f);

        if (stl) {
            qa.x -= qa.x * da.x; qa.y -= qa.y * da.y;
            qa.z -= qa.z * da.z; qa.w -= qa.w * da.w;
            qb.x -= qb.x * db.x; qb.y -= qb.y * db.y;
            qb.z -= qb.z * db.z; qb.w -= qb.w * db.w;
            float kx = 1.f - qa.x, ky = 1.f - qa.y, kz = 1.f - qa.z, kw = 1.f - qa.w;
            s0a += kx * pa.x + ky * pa.y + kz * pa.z + kw * pa.w;
            s1a += kx + ky + kz + kw;
            kx = 1.f - qb.x; ky = 1.f - qb.y; kz = 1.f - qb.z; kw = 1.f - qb.w;
            s0b += kx * pb.x + ky * pb.y + kz * pb.z + kw * pb.w;
            s1b += kx + ky + kz + kw;
        }
        Eprev = Ecur; Ecur = En;
    }
}

__global__ void __launch_bounds__(128, 3) reduce_stage_kernel(int srcsel) {
    int w    = (blockIdx.x << 2) + (threadIdx.x >> 5);
    int lane = threadIdx.x & 31;
    int pair = w / WPI;
    int rem  = w - pair * WPI;
    int sx   = rem / NSY;
    int sy   = rem - sx * NSY;
    int x0   = sx * OUTW;
    int r0   = sy * ROWS;
    int gx   = x0 - 4 + (lane << 2);

    bool colIn = (gx >= 0) && (gx < HW);
    bool stl   = (gx >= x0) && (gx < x0 + OUTW) && (gx < HW);

    const float* src = (srcsel == 1) ? g_imA : g_imB;
    const float* baseA = src + pair * NPIX;
    const float* baseB = src + (pair + 8) * NPIX;
    const float* qA = g_q + pair * NPIX;
    const float* qB = g_q + (pair + 8) * NPIX;
    const float* ppA = g_prob + (pair + 8) * NPIX;   // student skel x teacher prob
    const float* ppB = g_prob + pair * NPIX;         // teacher skel x student prob

    float s0a = 0.f, s1a = 0.f, s0b = 0.f, s1b = 0.f;
    bool edge = (sx == 0) || (sx == NSX - 1) || (sy == 0) || (sy == NSY - 1);
    if (!edge) redstage_body<false>(baseA, baseB, qA, qB, ppA, ppB, r0, gx, true,  stl, s0a, s1a, s0b, s1b);
    else       redstage_body<true >(baseA, baseB, qA, qB, ppA, ppB, r0, gx, colIn, stl, s0a, s1a, s0b, s1b);

    #pragma unroll
    for (int o = 16; o > 0; o >>= 1) {
        s0a += __shfl_down_sync(0xFFFFFFFFu, s0a, o);
        s1a += __shfl_down_sync(0xFFFFFFFFu, s1a, o);
        s0b += __shfl_down_sync(0xFFFFFFFFu, s0b, o);
        s1b += __shfl_down_sync(0xFFFFFFFFu, s1b, o);
    }
    __shared__ float sh[16];
    int wp = threadIdx.x >> 5;
    if (lane == 0) {
        sh[wp] = s0a; sh[4 + wp] = s1a; sh[8 + wp] = s0b; sh[12 + wp] = s1b;
    }
    __syncthreads();
    if (threadIdx.x == 0) {
        g_partials[blockIdx.x * 4 + 0] = sh[0]  + sh[1]  + sh[2]  + sh[3];
        g_partials[blockIdx.x * 4 + 1] = sh[4]  + sh[5]  + sh[6]  + sh[7];
        g_partials[blockIdx.x * 4 + 2] = sh[8]  + sh[9]  + sh[10] + sh[11];
        g_partials[blockIdx.x * 4 + 3] = sh[12] + sh[13] + sh[14] + sh[15];
    }
}

// ---------------- kernel 4: final clDice scalar ----------------------------------
__global__ void final_kernel(float* __restrict__ out) {
    const float EPSV = 1e-6f;
    int b = threadIdx.x;
    float acc = 0.f;
    if (b < NB) {
        float sp = 0.f, ss = 0.f, tp = 0.f, ts = 0.f;
        for (int c = 0; c < BPI; c++) {
            int base = (b * BPI + c) * 4;
            sp += g_partials[base + 0];
            ss += g_partials[base + 1];
            tp += g_partials[base + 2];
            ts += g_partials[base + 3];
        }
        float tprec = (sp + EPSV) / (ss + EPSV);
        float tsens = (tp + EPSV) / (ts + EPSV);
        float cl = (2.f * tprec * tsens + EPSV) / (tprec + tsens + EPSV);
        acc = 1.f - cl;
    }
    #pragma unroll
    for (int o = 4; o > 0; o >>= 1) acc += __shfl_down_sync(0xFFFFFFFFu, acc, o);
    if (threadIdx.x == 0) out[0] = acc * 0.125f;
}

// ---------------- launch ----------------------------------------------------------
extern "C" void kernel_launch(void* const* d_in, const int* in_sizes, int n_in,
                              void* d_out, int out_size) {
    const float* logits = (const float*)d_in[0];
    const float* mask   = (const float*)d_in[1];
    const int*   cidx   = (const int*)d_in[2];
    float* out = (float*)d_out;

    prob_kernel<<<(NB * NPIX / 4 + 255) / 256, 256>>>(logits, mask, cidx);

    fused_kernel<<<NBLK, 128>>>(0, 1, 1);           // stages 0,1 (init)
    int src = 1;
    for (int k = 1; k < 12; k++) {
        int dst = (src == 1) ? 2 : 1;
        fused_kernel<<<NBLK, 128>>>(src, dst, 0);
        src = dst;
    }
    reduce_stage_kernel<<<NBLK, 128>>>(src);        // stage 24 + reduction

    final_kernel<<<1, 32>>>(out);
}

// round 12
// speedup vs baseline: 1.1224x; 1.1224x over previous
#include <cuda_runtime.h>
#include <cuda_bf16.h>
#include <cstdint>

#define NB   8
#define NC   19
#define HW   512
#define NPIX (HW*HW)
#define NIMG 16
#define BIG  1e30f

#define OUTW 120
#define NSX  5
#define ROWS 16
#define NSY  (HW/ROWS)      // 32
#define WPI  (NSX*NSY)      // 160 warps per image
#define NBLK ((NIMG*WPI)/4) // 640 blocks of 4 warps
#define BPI  (WPI/4)        // 40 blocks per image

__device__ float g_prob[NIMG * NPIX];
__device__ float g_imA [NIMG * NPIX];
__device__ float g_imB [NIMG * NPIX];
__device__ float g_q   [NIMG * NPIX];
__device__ float g_partials[NBLK * 2];
__device__ unsigned g_barrier[16];

// ---------------- kernel 0: reset barriers (per graph replay) ---------------------
__global__ void reset_kernel() {
    if (threadIdx.x < 16) g_barrier[threadIdx.x] = 0u;
}

// ---------------- kernel 1: softmax class-prob + teacher clip (float4) ----------
__global__ void prob_kernel(const float* __restrict__ logits,
                            const float* __restrict__ mask,
                            const int* __restrict__ cidx) {
    int t = blockIdx.x * blockDim.x + threadIdx.x;
    if (t >= NB * NPIX / 4) return;
    int b = t >> 16;
    int p = (t & 65535) << 2;
    const float* lp = logits + (size_t)b * NC * NPIX + p;

    float4 v[NC];
    #pragma unroll
    for (int c = 0; c < NC; c++) v[c] = *(const float4*)(lp + (size_t)c * NPIX);

    float4 m = v[0];
    #pragma unroll
    for (int c = 1; c < NC; c++) {
        m.x = fmaxf(m.x, v[c].x); m.y = fmaxf(m.y, v[c].y);
        m.z = fmaxf(m.z, v[c].z); m.w = fmaxf(m.w, v[c].w);
    }
    int ci = *cidx;
    float4 s = {0,0,0,0}, tg = {0,0,0,0};
    #pragma unroll
    for (int c = 0; c < NC; c++) {
        float4 e;
        e.x = __expf(v[c].x - m.x); e.y = __expf(v[c].y - m.y);
        e.z = __expf(v[c].z - m.z); e.w = __expf(v[c].w - m.w);
        s.x += e.x; s.y += e.y; s.z += e.z; s.w += e.w;
        if (c == ci) tg = e;
    }
    float4 pr;
    pr.x = fminf(fmaxf(tg.x / s.x, 0.f), 1.f);
    pr.y = fminf(fmaxf(tg.y / s.y, 0.f), 1.f);
    pr.z = fminf(fmaxf(tg.z / s.z, 0.f), 1.f);
    pr.w = fminf(fmaxf(tg.w / s.w, 0.f), 1.f);
    *(float4*)(g_prob + b * NPIX + p) = pr;

    float4 mk = *(const float4*)(mask + b * NPIX + p);
    mk.x = fminf(fmaxf(mk.x, 0.f), 1.f);
    mk.y = fminf(fmaxf(mk.y, 0.f), 1.f);
    mk.z = fminf(fmaxf(mk.z, 0.f), 1.f);
    mk.w = fminf(fmaxf(mk.w, 0.f), 1.f);
    *(float4*)(g_prob + (NB + b) * NPIX + p) = mk;
}

// ---------------- morphology primitives -------------------------------------------
__device__ __forceinline__ float4 ldrow_e(const float* __restrict__ b, int q, int gx, bool ok) {
    if (ok && (unsigned)q < HW) return *(const float4*)(b + q * HW + gx);
    float4 r; r.x = r.y = r.z = r.w = BIG; return r;
}

template<bool EDGE>
__device__ __forceinline__ float4 ld(const float* __restrict__ b, int q, int gx, bool ok) {
    if (!EDGE) return *(const float4*)(b + q * HW + gx);
    return ldrow_e(b, q, gx, ok);
}

__device__ __forceinline__ float4 ero3(float4 a, float4 b, float4 c) {
    float4 v;
    v.x = fminf(fminf(a.x, b.x), c.x);
    v.y = fminf(fminf(a.y, b.y), c.y);
    v.z = fminf(fminf(a.z, b.z), c.z);
    v.w = fminf(fminf(a.w, b.w), c.w);
    float vl = __shfl_up_sync(0xFFFFFFFFu, v.w, 1);
    float vr = __shfl_down_sync(0xFFFFFFFFu, v.x, 1);
    float m01 = fminf(v.x, v.y), m12 = fminf(v.y, v.z), m23 = fminf(v.z, v.w);
    float4 e;
    e.x = fminf(vl, m01);
    e.y = fminf(m01, v.z);
    e.z = fminf(m12, v.w);
    e.w = fminf(m23, vr);
    return e;
}

__device__ __forceinline__ float4 dil3(float4 a, float4 b, float4 c) {
    float4 t;
    t.x = fmaxf(fmaxf(a.x, b.x), c.x);
    t.y = fmaxf(fmaxf(a.y, b.y), c.y);
    t.z = fmaxf(fmaxf(a.z, b.z), c.z);
    t.w = fmaxf(fmaxf(a.w, b.w), c.w);
    float tl = __shfl_up_sync(0xFFFFFFFFu, t.w, 1);
    float tr = __shfl_down_sync(0xFFFFFFFFu, t.x, 1);
    float M01 = fmaxf(t.x, t.y), M12 = fmaxf(t.y, t.z), M23 = fmaxf(t.z, t.w);
    float4 d;
    d.x = fmaxf(tl, M01);
    d.y = fmaxf(M01, t.z);
    d.z = fmaxf(M12, t.w);
    d.w = fmaxf(M23, tr);
    return d;
}

__device__ __forceinline__ float4 msel(float4 v, bool in, float pad) {
    float4 r;
    r.x = in ? v.x : pad;
    r.y = in ? v.y : pad;
    r.z = in ? v.z : pad;
    r.w = in ? v.w : pad;
    return r;
}

template<bool EDGE>
__device__ __forceinline__ float4 mk(float4 v, bool in, float pad) {
    if (!EDGE) return v;
    return msel(v, in, pad);
}

// ---------------- fused double-stage body (proven 80-reg version) ------------------
template<bool EDGE>
__device__ __forceinline__ void fused_body(
    const float* __restrict__ base, float* __restrict__ outp,
    float* __restrict__ qp, int r0, int gx, bool colIn, bool stl, bool init)
{
    float4 imm3 = ld<EDGE>(base, r0 - 3, gx, colIn);
    float4 imr[6];
    imr[4] = ld<EDGE>(base, r0 - 2, gx, colIn);
    imr[5] = ld<EDGE>(base, r0 - 1, gx, colIn);
    imr[0] = ld<EDGE>(base, r0 + 0, gx, colIn);
    imr[1] = ld<EDGE>(base, r0 + 1, gx, colIn);
    imr[2] = ld<EDGE>(base, r0 + 2, gx, colIn);
    imr[3] = ld<EDGE>(base, r0 + 3, gx, colIn);

    float4 e1[4], e2[3];
    float4 e1m2 = ero3(imm3, imr[4], imr[5]);
    e1[3] = ero3(imr[4], imr[5], imr[0]);
    e1[0] = ero3(imr[5], imr[0], imr[1]);
    e1[1] = ero3(imr[0], imr[1], imr[2]);

    {
        bool inA = colIn && ((unsigned)(r0 - 2) < HW);
        bool inB = colIn && ((unsigned)(r0 - 1) < HW);
        e2[2] = ero3(mk<EDGE>(e1m2, inA, BIG), mk<EDGE>(e1[3], inB, BIG),
                     mk<EDGE>(e1[0], colIn, BIG));
        e2[0] = ero3(mk<EDGE>(e1[3], inB, BIG), mk<EDGE>(e1[0], colIn, BIG),
                     mk<EDGE>(e1[1], colIn, BIG));
    }

    #pragma unroll
    for (int i = 0; i < ROWS; i++) {
        int r = r0 + i;
        imr[(i + 4) % 6] = ld<EDGE>(base, r + 4, gx, colIn);

        int o = r * HW + gx;
        float4 q;
        if (stl && !init) q = *(const float4*)(qp + o);

        bool inRm1 = colIn && ((unsigned)(r - 1) < HW);
        bool inRp1 = colIn && ((unsigned)(r + 1) < HW);
        bool inRp2 = colIn && ((unsigned)(r + 2) < HW);

        e1[(i + 2) % 4] = ero3(imr[(i + 1) % 6], imr[(i + 2) % 6], imr[(i + 3) % 6]);

        e2[(i + 1) % 3] = ero3(mk<EDGE>(e1[i % 4],       colIn, BIG),
                               mk<EDGE>(e1[(i + 1) % 4], inRp1, BIG),
                               mk<EDGE>(e1[(i + 2) % 4], inRp2, BIG));

        float4 d1 = dil3(mk<EDGE>(e1[(i + 3) % 4], inRm1, -BIG),
                         mk<EDGE>(e1[i % 4],       colIn, -BIG),
                         mk<EDGE>(e1[(i + 1) % 4], inRp1, -BIG));

        float4 d2 = dil3(mk<EDGE>(e2[(i + 2) % 3], inRm1, -BIG),
                         mk<EDGE>(e2[i % 3],       colIn, -BIG),
                         mk<EDGE>(e2[(i + 1) % 3], inRp1, -BIG));

        float4 ia = imr[i % 6];
        float4 da, db;
        da.x = fmaxf(ia.x - d1.x, 0.f);
        da.y = fmaxf(ia.y - d1.y, 0.f);
        da.z = fmaxf(ia.z - d1.z, 0.f);
        da.w = fmaxf(ia.w - d1.w, 0.f);
        float4 eb = e1[i % 4];
        db.x = fmaxf(eb.x - d2.x, 0.f);
        db.y = fmaxf(eb.y - d2.y, 0.f);
        db.z = fmaxf(eb.z - d2.z, 0.f);
        db.w = fmaxf(eb.w - d2.w, 0.f);

        if (stl) {
            if (init) {
                q.x = 1.f - da.x; q.y = 1.f - da.y;
                q.z = 1.f - da.z; q.w = 1.f - da.w;
            } else {
                q.x -= q.x * da.x; q.y -= q.y * da.y;
                q.z -= q.z * da.z; q.w -= q.w * da.w;
            }
            q.x -= q.x * db.x; q.y -= q.y * db.y;
            q.z -= q.z * db.z; q.w -= q.w * db.w;
            *(float4*)(qp + o)   = q;
            *(float4*)(outp + o) = e2[i % 3];
        }
    }
}

// ---------------- last stage + partial reduction body ------------------------------
template<bool EDGE>
__device__ __forceinline__ void redstage_body(
    const float* __restrict__ base, const float* __restrict__ qp,
    const float* __restrict__ pp,
    int r0, int gx, bool colIn, bool stl, float& s0, float& s1)
{
    float4 ring[6];
    #pragma unroll
    for (int j = 0; j < 6; j++) ring[j] = ld<EDGE>(base, r0 - 2 + j, gx, colIn);

    bool inM1 = colIn && ((unsigned)(r0 - 1) < HW);
    float4 Eprev = mk<EDGE>(ero3(ring[0], ring[1], ring[2]), inM1, -BIG);
    float4 Ecur  = mk<EDGE>(ero3(ring[1], ring[2], ring[3]), colIn, -BIG);

    #pragma unroll
    for (int i = 0; i < ROWS; i++) {
        int r = r0 + i;
        ring[i % 6] = ld<EDGE>(base, r + 4, gx, colIn);
        int o = r * HW + gx;
        float4 q, pr;
        if (stl) {
            q  = *(const float4*)(qp + o);
            pr = *(const float4*)(pp + o);
        }

        bool inP1 = colIn && ((unsigned)(r + 1) < HW);
        float4 En = mk<EDGE>(ero3(ring[(i + 2) % 6], ring[(i + 3) % 6], ring[(i + 4) % 6]),
                             inP1, -BIG);
        float4 dd = dil3(Eprev, Ecur, En);
        float4 ic = ring[(i + 2) % 6];
        float4 delta;
        delta.x = fmaxf(ic.x - dd.x, 0.f);
        delta.y = fmaxf(ic.y - dd.y, 0.f);
        delta.z = fmaxf(ic.z - dd.z, 0.f);
        delta.w = fmaxf(ic.w - dd.w, 0.f);

        if (stl) {
            q.x -= q.x * delta.x;
            q.y -= q.y * delta.y;
            q.z -= q.z * delta.z;
            q.w -= q.w * delta.w;
            float kx = 1.f - q.x, ky = 1.f - q.y, kz = 1.f - q.z, kw = 1.f - q.w;
            s0 += kx * pr.x + ky * pr.y + kz * pr.z + kw * pr.w;
            s1 += kx + ky + kz + kw;
        }
        Eprev = Ecur; Ecur = En;
    }
}

// ---------------- grid barrier (all NBLK CTAs co-resident) -------------------------
__device__ __forceinline__ void gridbar(int s) {
    __syncthreads();
    if (threadIdx.x == 0) {
        __threadfence();                      // release (cumulative)
        unsigned old = atomicAdd(&g_barrier[s], 1u);
        if (old + 1u < (unsigned)NBLK) {
            while (*(volatile unsigned*)&g_barrier[s] < (unsigned)NBLK) { }
        }
        __threadfence();                      // acquire
    }
    __syncthreads();
}

// ---------------- persistent kernel: 12 fused stages + final stage + reduction -----
__global__ void __launch_bounds__(128, 5) persist_kernel(float* __restrict__ out) {
    int w    = (blockIdx.x << 2) + (threadIdx.x >> 5);
    int lane = threadIdx.x & 31;
    int img  = w / WPI;
    int rem  = w - img * WPI;
    int sx   = rem / NSY;
    int sy   = rem - sx * NSY;
    int x0   = sx * OUTW;
    int r0   = sy * ROWS;
    int gx   = x0 - 4 + (lane << 2);

    bool colIn = (gx >= 0) && (gx < HW);
    bool stl   = (gx >= x0) && (gx < x0 + OUTW) && (gx < HW);
    bool edge  = (sx == 0) || (sx == NSX - 1) || (sy == 0) || (sy == NSY - 1);

    float* __restrict__ qp = g_q + img * NPIX;

    // 12 fused double-stages (stages 0..23)
    #pragma unroll 1
    for (int s = 0; s < 12; s++) {
        const float* base = (s == 0) ? (g_prob + img * NPIX)
                          : (((s & 1) ? g_imA : g_imB) + img * NPIX);
        float* outp = (((s & 1) ? g_imB : g_imA) + img * NPIX);
        bool init = (s == 0);
        if (!edge) fused_body<false>(base, outp, qp, r0, gx, true,  stl, init);
        else       fused_body<true >(base, outp, qp, r0, gx, colIn, stl, init);
        gridbar(s);
    }

    // stage 24 + partial reduction (last fused wrote to imB when s=11 odd)
    {
        const float* base = g_imB + img * NPIX;
        const float* pp   = g_prob + (img ^ 8) * NPIX;
        float s0 = 0.f, s1 = 0.f;
        if (!edge) redstage_body<false>(base, qp, pp, r0, gx, true,  stl, s0, s1);
        else       redstage_body<true >(base, qp, pp, r0, gx, colIn, stl, s0, s1);

        #pragma unroll
        for (int o = 16; o > 0; o >>= 1) {
            s0 += __shfl_down_sync(0xFFFFFFFFu, s0, o);
            s1 += __shfl_down_sync(0xFFFFFFFFu, s1, o);
        }
        __shared__ float sh[8];
        int wp = threadIdx.x >> 5;
        if (lane == 0) { sh[wp] = s0; sh[4 + wp] = s1; }
        __syncthreads();
        if (threadIdx.x == 0) {
            g_partials[blockIdx.x * 2]     = sh[0] + sh[1] + sh[2] + sh[3];
            g_partials[blockIdx.x * 2 + 1] = sh[4] + sh[5] + sh[6] + sh[7];
        }
    }
    gridbar(12);

    // final clDice scalar: block 0, one warp
    if (blockIdx.x == 0 && threadIdx.x < 32) {
        const float EPSV = 1e-6f;
        int b = threadIdx.x;
        float acc = 0.f;
        if (b < NB) {
            float sp = 0.f, ss = 0.f, tp = 0.f, ts = 0.f;
            for (int c = 0; c < BPI; c++) {
                sp += g_partials[(b * BPI + c) * 2];
                ss += g_partials[(b * BPI + c) * 2 + 1];
                tp += g_partials[((b + 8) * BPI + c) * 2];
                ts += g_partials[((b + 8) * BPI + c) * 2 + 1];
            }
            float tprec = (sp + EPSV) / (ss + EPSV);
            float tsens = (tp + EPSV) / (ts + EPSV);
            float cl = (2.f * tprec * tsens + EPSV) / (tprec + tsens + EPSV);
            acc = 1.f - cl;
        }
        #pragma unroll
        for (int o = 4; o > 0; o >>= 1) acc += __shfl_down_sync(0xFFFFFFFFu, acc, o);
        if (threadIdx.x == 0) out[0] = acc * 0.125f;
    }
}

// ---------------- launch ----------------------------------------------------------
extern "C" void kernel_launch(void* const* d_in, const int* in_sizes, int n_in,
                              void* d_out, int out_size) {
    const float* logits = (const float*)d_in[0];
    const float* mask   = (const float*)d_in[1];
    const int*   cidx   = (const int*)d_in[2];
    float* out = (float*)d_out;

    reset_kernel<<<1, 32>>>();
    prob_kernel<<<(NB * NPIX / 4 + 255) / 256, 256>>>(logits, mask, cidx);
    persist_kernel<<<NBLK, 128>>>(out);
}